// round 12
// baseline (speedup 1.0000x reference)
#include <cuda_runtime.h>
#include <cuda_fp16.h>
#include <cstdint>

#define F 128
#define MAXN 131072
#define MAXE 2097152
#define MAXG 1024
#define NBLK_SCAN 128   // MAXN / 1024

// -------- scratch (device globals; no runtime allocation) --------
__device__ __half g_Th [(size_t)MAXN * F];  // layer-1 messages (fp16)
__device__ __half g_Th2[(size_t)MAXN * F];  // layer-2 messages (fp16)
__device__ float  g_dis[MAXN];
__device__ int    g_deg[MAXN];
__device__ int    g_rowoff[MAXN + 1];
__device__ int    g_cur[MAXN];
__device__ int    g_ssrc[MAXE];
__device__ int    g_blk[NBLK_SCAN];
__device__ int    g_blkoff[NBLK_SCAN];
__device__ int    g_cnt[MAXG];
__device__ int    g_flags;

// -------- index helpers --------
__device__ __forceinline__ int idx_at(const void* p, long long i, int is64) {
    return is64 ? (int)((const long long*)p)[i] : ((const int*)p)[i];
}

// -------- detect (block 0) + init (all blocks), fused --------
__global__ void k_detect_init(const void* ei, int twoE, const void* batch,
                              float* out, int out_elems, int n) {
    int i = blockIdx.x * blockDim.x + threadIdx.x;
    if (i < n)         g_deg[i] = 0;
    if (i < MAXG)      g_cnt[i] = 0;
    if (i < out_elems) out[i]   = 0.0f;
    if (blockIdx.x == 0 && threadIdx.x == 0) {
        const int* e32 = (const int*)ei;
        const int* b32 = (const int*)batch;
        int e64 = 1, b64 = 1;
        int m1 = (twoE / 2) & ~1;
        for (int k = 1; k < 64; k += 2)      if (e32[k] != 0)      { e64 = 0; break; }
        if (e64) for (int k = 1; k < 64; k += 2) if (e32[m1 + k] != 0) { e64 = 0; break; }
        int m2 = (n / 2) & ~1;
        for (int k = 1; k < 64 && m2 + k < n; k += 2) if (b32[m2 + k] != 0) { b64 = 0; break; }
        g_flags = (e64 ? 1 : 0) | (b64 ? 2 : 0);
    }
}

__global__ void k_degcnt(const void* ei, int E, const void* batch, int n) {
    int i = blockIdx.x * blockDim.x + threadIdx.x;
    int fl = g_flags;
    if (i < E) {
        int d = idx_at(ei, (long long)E + i, fl & 1);
        atomicAdd(&g_deg[d], 1);
    }
    if (i < n) {
        int b = idx_at(batch, i, (fl >> 1) & 1);
        atomicAdd(&g_cnt[b], 1);
    }
}

__global__ void k_scan1(int n) {
    __shared__ int s[256];
    int blk = blockIdx.x;
    int base = blk * 1024;
    int t = threadIdx.x;
    int v[4]; int sum = 0;
#pragma unroll
    for (int j = 0; j < 4; j++) {
        int i = base + t * 4 + j;
        v[j] = (i < n) ? g_deg[i] : 0;
        sum += v[j];
    }
    s[t] = sum;
    __syncthreads();
    for (int off = 1; off < 256; off <<= 1) {
        int y = (t >= off) ? s[t - off] : 0;
        __syncthreads();
        s[t] += y;
        __syncthreads();
    }
    int run = s[t] - sum;
#pragma unroll
    for (int j = 0; j < 4; j++) {
        int i = base + t * 4 + j;
        if (i < n) g_rowoff[i] = run;
        run += v[j];
    }
    if (t == 255) g_blk[blk] = s[255];
}

__global__ void k_scan2(int nblk) {
    __shared__ int s[NBLK_SCAN];
    int t = threadIdx.x;
    int v = (t < nblk) ? g_blk[t] : 0;
    s[t] = v;
    __syncthreads();
    for (int off = 1; off < NBLK_SCAN; off <<= 1) {
        int y = (t >= off) ? s[t - off] : 0;
        __syncthreads();
        s[t] += y;
        __syncthreads();
    }
    g_blkoff[t] = s[t] - v;
}

__global__ void k_scan3(int n, int E) {
    int i = blockIdx.x * blockDim.x + threadIdx.x;
    if (i < n) {
        int r = g_rowoff[i] + g_blkoff[i >> 10];
        g_rowoff[i] = r;
        g_cur[i] = r;
        g_dis[i] = rsqrtf((float)(g_deg[i] + 1));
    }
    if (i == 0) g_rowoff[n] = E;
}

__global__ void k_place(const void* __restrict__ ei, int E) {
    int e = blockIdx.x * blockDim.x + threadIdx.x;
    if (e >= E) return;
    int fl = g_flags & 1;
    int s = idx_at(ei, e, fl);
    int d = idx_at(ei, (long long)E + e, fl);
    int slot = atomicAdd(&g_cur[d], 1);
    g_ssrc[slot] = s;
}

// -------- fp16 mma m16n8k16 --------
__device__ __forceinline__ void mma_f16(float* c, const unsigned* a, const unsigned* b) {
    asm volatile("mma.sync.aligned.m16n8k16.row.col.f32.f16.f16.f32 "
                 "{%0,%1,%2,%3}, {%4,%5,%6,%7}, {%8,%9}, {%0,%1,%2,%3};"
                 : "+f"(c[0]), "+f"(c[1]), "+f"(c[2]), "+f"(c[3])
                 : "r"(a[0]), "r"(a[1]), "r"(a[2]), "r"(a[3]),
                   "r"(b[0]), "r"(b[1]));
}

__device__ __forceinline__ unsigned h2u(__half2 h) { return *(unsigned*)&h; }

__device__ __forceinline__ float4 h4tof4(uint2 r) {
    float2 fa = __half22float2(*(__half2*)&r.x);
    float2 fb = __half22float2(*(__half2*)&r.y);
    return make_float4(fa.x, fa.y, fb.x, fb.y);
}

// -------- GEMM layer 1 (fp16 m16n8k16): Th = half((x @ W1) * dis) --------
__global__ void __launch_bounds__(256) k_gemm1(const float* __restrict__ A,
                                               const float* __restrict__ W,
                                               int n) {
    __shared__ __half As[128][40];   // [row][k]; frag bank = 20*lq+lr distinct
    __shared__ __half Ws[32][136];

    const int tid = threadIdx.x;
    const int lane = tid & 31;
    const int wid = tid >> 5;
    const int warp_m = wid & 1;
    const int warp_n = wid >> 1;
    const int row0 = blockIdx.x * 128;
    const int lq = lane >> 2;
    const int lr = lane & 3;

    float c[4][4][4];
#pragma unroll
    for (int i = 0; i < 4; i++)
#pragma unroll
        for (int j = 0; j < 4; j++)
#pragma unroll
            for (int r = 0; r < 4; r++) c[i][j][r] = 0.0f;

    for (int k0 = 0; k0 < F; k0 += 32) {
#pragma unroll
        for (int it = 0; it < 4; it++) {
            int idx = tid + it * 256;
            int k = idx >> 5, c4 = idx & 31;
            float4 w = ((const float4*)(W + (size_t)(k0 + k) * F))[c4];
            *(__half2*)&Ws[k][c4 * 4 + 0] = __floats2half2_rn(w.x, w.y);
            *(__half2*)&Ws[k][c4 * 4 + 2] = __floats2half2_rn(w.z, w.w);
        }
#pragma unroll
        for (int it = 0; it < 4; it++) {
            int idx = tid + it * 256;
            int r = idx >> 3, kp = idx & 7;
            int row = row0 + r;
            float4 a = make_float4(0.f, 0.f, 0.f, 0.f);
            if (row < n) a = ((const float4*)(A + (size_t)row * F + k0))[kp];
            *(__half2*)&As[r][kp * 4 + 0] = __floats2half2_rn(a.x, a.y);
            *(__half2*)&As[r][kp * 4 + 2] = __floats2half2_rn(a.z, a.w);
        }
        __syncthreads();

#pragma unroll
        for (int ks = 0; ks < 2; ks++) {
            const int kk = ks * 16;
            unsigned ar[4][4];
#pragma unroll
            for (int tm = 0; tm < 4; tm++) {
                int r = warp_m * 64 + tm * 16 + lq;
                ar[tm][0] = *(unsigned*)&As[r][kk + 2 * lr];
                ar[tm][1] = *(unsigned*)&As[r + 8][kk + 2 * lr];
                ar[tm][2] = *(unsigned*)&As[r][kk + 2 * lr + 8];
                ar[tm][3] = *(unsigned*)&As[r + 8][kk + 2 * lr + 8];
            }
            unsigned br[4][2];
#pragma unroll
            for (int tn = 0; tn < 4; tn++) {
                int col = warp_n * 32 + tn * 8 + lq;
                br[tn][0] = h2u(__halves2half2(Ws[kk + 2 * lr][col],
                                               Ws[kk + 2 * lr + 1][col]));
                br[tn][1] = h2u(__halves2half2(Ws[kk + 2 * lr + 8][col],
                                               Ws[kk + 2 * lr + 9][col]));
            }
#pragma unroll
            for (int tn = 0; tn < 4; tn++)
#pragma unroll
                for (int tm = 0; tm < 4; tm++)
                    mma_f16(c[tm][tn], ar[tm], br[tn]);
        }
        __syncthreads();
    }

#pragma unroll
    for (int tm = 0; tm < 4; tm++) {
        int r0 = row0 + warp_m * 64 + tm * 16 + lq;
        int r1 = r0 + 8;
        float d0 = (r0 < n) ? g_dis[r0] : 0.f;
        float d1 = (r1 < n) ? g_dis[r1] : 0.f;
#pragma unroll
        for (int tn = 0; tn < 4; tn++) {
            int col = warp_n * 32 + tn * 8 + lr * 2;
            if (r0 < n)
                *(__half2*)(g_Th + (size_t)r0 * F + col) =
                    __floats2half2_rn(c[tm][tn][0] * d0, c[tm][tn][1] * d0);
            if (r1 < n)
                *(__half2*)(g_Th + (size_t)r1 * F + col) =
                    __floats2half2_rn(c[tm][tn][2] * d1, c[tm][tn][3] * d1);
        }
    }
}

// -------- FUSED: agg layer-1 (CSR gather from Th) -> smem -> GEMM2 -> Th2 ----
__global__ void __launch_bounds__(256) k_agg_gemm2(const float* __restrict__ W,
                                                   const float* __restrict__ b1,
                                                   int n) {
    __shared__ __half As[128][136];  // full A tile; frag bank = 4*lq+lr+const distinct
    __shared__ __half Ws[32][136];

    const __half* __restrict__ T = g_Th;
    const int tid = threadIdx.x;
    const int lane = tid & 31;
    const int wid = tid >> 5;
    const int row0 = blockIdx.x * 128;

    // ---- Phase A: aggregate + relu(dis*acc+b1) -> As (fp16) ----
    {
        float4 bb = ((const float4*)b1)[lane];
        for (int i = wid; i < 128; i += 8) {
            int node = row0 + i;
            float4 acc = make_float4(0.f, 0.f, 0.f, 0.f);
            if (node < n) {
                acc = h4tof4(((const uint2*)(T + (size_t)node * F))[lane]);  // self
                int beg = g_rowoff[node];
                int end = g_rowoff[node + 1];
                int j = beg;
                for (; j + 4 <= end; j += 4) {
                    int s0 = g_ssrc[j], s1 = g_ssrc[j + 1];
                    int s2 = g_ssrc[j + 2], s3 = g_ssrc[j + 3];
                    float4 a = h4tof4(((const uint2*)(T + (size_t)s0 * F))[lane]);
                    float4 b = h4tof4(((const uint2*)(T + (size_t)s1 * F))[lane]);
                    float4 c = h4tof4(((const uint2*)(T + (size_t)s2 * F))[lane]);
                    float4 d = h4tof4(((const uint2*)(T + (size_t)s3 * F))[lane]);
                    acc.x += a.x + b.x + c.x + d.x;
                    acc.y += a.y + b.y + c.y + d.y;
                    acc.z += a.z + b.z + c.z + d.z;
                    acc.w += a.w + b.w + c.w + d.w;
                }
                for (; j < end; j++) {
                    int s = g_ssrc[j];
                    float4 a = h4tof4(((const uint2*)(T + (size_t)s * F))[lane]);
                    acc.x += a.x; acc.y += a.y; acc.z += a.z; acc.w += a.w;
                }
                float dv = g_dis[node];
                acc.x = fmaxf(fmaf(dv, acc.x, bb.x), 0.f);
                acc.y = fmaxf(fmaf(dv, acc.y, bb.y), 0.f);
                acc.z = fmaxf(fmaf(dv, acc.z, bb.z), 0.f);
                acc.w = fmaxf(fmaf(dv, acc.w, bb.w), 0.f);
            }
            *(__half2*)&As[i][4 * lane + 0] = __floats2half2_rn(acc.x, acc.y);
            *(__half2*)&As[i][4 * lane + 2] = __floats2half2_rn(acc.z, acc.w);
        }
    }
    __syncthreads();

    // ---- Phase B: GEMM As @ W2, epilogue *dis -> Th2 ----
    const int warp_m = wid & 1;
    const int warp_n = wid >> 1;
    const int lq = lane >> 2;
    const int lr = lane & 3;

    float c[4][4][4];
#pragma unroll
    for (int i = 0; i < 4; i++)
#pragma unroll
        for (int j = 0; j < 4; j++)
#pragma unroll
            for (int r = 0; r < 4; r++) c[i][j][r] = 0.0f;

    for (int k0 = 0; k0 < F; k0 += 32) {
#pragma unroll
        for (int it = 0; it < 4; it++) {
            int idx = tid + it * 256;
            int k = idx >> 5, c4 = idx & 31;
            float4 w = ((const float4*)(W + (size_t)(k0 + k) * F))[c4];
            *(__half2*)&Ws[k][c4 * 4 + 0] = __floats2half2_rn(w.x, w.y);
            *(__half2*)&Ws[k][c4 * 4 + 2] = __floats2half2_rn(w.z, w.w);
        }
        __syncthreads();

#pragma unroll
        for (int ks = 0; ks < 2; ks++) {
            const int kk = k0 + ks * 16;
            unsigned ar[4][4];
#pragma unroll
            for (int tm = 0; tm < 4; tm++) {
                int r = warp_m * 64 + tm * 16 + lq;
                ar[tm][0] = *(unsigned*)&As[r][kk + 2 * lr];
                ar[tm][1] = *(unsigned*)&As[r + 8][kk + 2 * lr];
                ar[tm][2] = *(unsigned*)&As[r][kk + 2 * lr + 8];
                ar[tm][3] = *(unsigned*)&As[r + 8][kk + 2 * lr + 8];
            }
            const int kl = ks * 16;
            unsigned br[4][2];
#pragma unroll
            for (int tn = 0; tn < 4; tn++) {
                int col = warp_n * 32 + tn * 8 + lq;
                br[tn][0] = h2u(__halves2half2(Ws[kl + 2 * lr][col],
                                               Ws[kl + 2 * lr + 1][col]));
                br[tn][1] = h2u(__halves2half2(Ws[kl + 2 * lr + 8][col],
                                               Ws[kl + 2 * lr + 9][col]));
            }
#pragma unroll
            for (int tn = 0; tn < 4; tn++)
#pragma unroll
                for (int tm = 0; tm < 4; tm++)
                    mma_f16(c[tm][tn], ar[tm], br[tn]);
        }
        __syncthreads();
    }

#pragma unroll
    for (int tm = 0; tm < 4; tm++) {
        int r0 = row0 + warp_m * 64 + tm * 16 + lq;
        int r1 = r0 + 8;
        float d0 = (r0 < n) ? g_dis[r0] : 0.f;
        float d1 = (r1 < n) ? g_dis[r1] : 0.f;
#pragma unroll
        for (int tn = 0; tn < 4; tn++) {
            int col = warp_n * 32 + tn * 8 + lr * 2;
            if (r0 < n)
                *(__half2*)(g_Th2 + (size_t)r0 * F + col) =
                    __floats2half2_rn(c[tm][tn][0] * d0, c[tm][tn][1] * d0);
            if (r1 < n)
                *(__half2*)(g_Th2 + (size_t)r1 * F + col) =
                    __floats2half2_rn(c[tm][tn][2] * d1, c[tm][tn][3] * d1);
        }
    }
}

// -------- agg layer 2 + fused pooling: red.add relu(dis*acc+b2) into out ----
__global__ void __launch_bounds__(256) k_agg2(int n, const void* __restrict__ batch,
                                              const float* __restrict__ b2,
                                              float* __restrict__ out) {
    const __half* __restrict__ T = g_Th2;
    int w = (blockIdx.x * blockDim.x + threadIdx.x) >> 5;
    int lane = threadIdx.x & 31;
    if (w >= n) return;

    int beg = g_rowoff[w];
    int end = g_rowoff[w + 1];

    float4 acc = h4tof4(((const uint2*)(T + (size_t)w * F))[lane]);   // self loop

    int j = beg;
    for (; j + 4 <= end; j += 4) {
        int s0 = g_ssrc[j], s1 = g_ssrc[j + 1], s2 = g_ssrc[j + 2], s3 = g_ssrc[j + 3];
        float4 a = h4tof4(((const uint2*)(T + (size_t)s0 * F))[lane]);
        float4 b = h4tof4(((const uint2*)(T + (size_t)s1 * F))[lane]);
        float4 c = h4tof4(((const uint2*)(T + (size_t)s2 * F))[lane]);
        float4 d = h4tof4(((const uint2*)(T + (size_t)s3 * F))[lane]);
        acc.x += a.x + b.x + c.x + d.x;
        acc.y += a.y + b.y + c.y + d.y;
        acc.z += a.z + b.z + c.z + d.z;
        acc.w += a.w + b.w + c.w + d.w;
    }
    for (; j < end; j++) {
        int s = g_ssrc[j];
        float4 a = h4tof4(((const uint2*)(T + (size_t)s * F))[lane]);
        acc.x += a.x; acc.y += a.y; acc.z += a.z; acc.w += a.w;
    }

    int g = idx_at(batch, w, (g_flags >> 1) & 1);
    float dv = g_dis[w];
    float4 bb = ((const float4*)b2)[lane];
    float4 r;
    r.x = fmaxf(fmaf(dv, acc.x, bb.x), 0.f);
    r.y = fmaxf(fmaf(dv, acc.y, bb.y), 0.f);
    r.z = fmaxf(fmaf(dv, acc.z, bb.z), 0.f);
    r.w = fmaxf(fmaf(dv, acc.w, bb.w), 0.f);
    float* p = out + (size_t)g * F + lane * 4;
    asm volatile("red.global.add.v4.f32 [%0], {%1,%2,%3,%4};"
                 :: "l"(p), "f"(r.x), "f"(r.y), "f"(r.z), "f"(r.w)
                 : "memory");
}

__global__ void k_div(float* out, int total) {
    int i = blockIdx.x * blockDim.x + threadIdx.x;
    if (i < total) {
        int g = i >> 7;
        int c = g_cnt[g];
        out[i] = out[i] / (float)(c > 1 ? c : 1);
    }
}

// -------- launch --------
extern "C" void kernel_launch(void* const* d_in, const int* in_sizes, int n_in,
                              void* d_out, int out_size) {
    const float* x   = (const float*)d_in[0];
    const void*  ei  = d_in[1];
    const void*  bat = d_in[2];
    const float* W1  = (const float*)d_in[3];
    const float* b1  = (const float*)d_in[4];
    const float* W2  = (const float*)d_in[5];
    const float* b2  = (const float*)d_in[6];
    float* out = (float*)d_out;

    int n = in_sizes[2];
    if (n > MAXN) n = MAXN;
    int E = in_sizes[1] / 2;
    if (E > MAXE) E = MAXE;

    int initN = (n > out_size) ? n : out_size;
    k_detect_init<<<(initN + 255) / 256, 256>>>(ei, 2 * E, bat, out, out_size, n);

    int degN = (E > n) ? E : n;
    k_degcnt<<<(degN + 255) / 256, 256>>>(ei, E, bat, n);

    int nblk = (n + 1023) / 1024;
    k_scan1<<<nblk, 256>>>(n);
    k_scan2<<<1, NBLK_SCAN>>>(nblk);
    k_scan3<<<(n + 255) / 256, 256>>>(n, E);

    k_place<<<(E + 255) / 256, 256>>>(ei, E);

    int gblocks = (n + 127) / 128;
    int ablocks = (n + 7) / 8;

    k_gemm1<<<gblocks, 256>>>(x, W1, n);
    k_agg_gemm2<<<gblocks, 256>>>(W2, b1, n);
    k_agg2<<<ablocks, 256>>>(n, bat, b2, out);
    k_div<<<(out_size + 255) / 256, 256>>>(out, out_size);
}

// round 13
// speedup vs baseline: 1.2789x; 1.2789x over previous
#include <cuda_runtime.h>
#include <cuda_fp16.h>
#include <cstdint>

#define F 128
#define MAXN 131072
#define MAXE 2097152
#define MAXG 1024
#define NBLK_SCAN 128   // MAXN / 1024

// -------- scratch (device globals; no runtime allocation) --------
__device__ __half g_Th[(size_t)MAXN * F];  // messages (fp16), reused both layers
__device__ float  g_A1[(size_t)MAXN * F];  // layer-1 aggregated (fp32)
__device__ float  g_dis[MAXN];
__device__ int    g_deg[MAXN];
__device__ int    g_rowoff[MAXN];          // PARTIAL prefix (add g_blkoff[i>>10])
__device__ int    g_eslot[MAXE];           // per-edge rank within its dst
__device__ int    g_ssrc[MAXE];            // src ids sorted by dst
__device__ int    g_blk[NBLK_SCAN];
__device__ int    g_blkoff[NBLK_SCAN];
__device__ int    g_cnt[MAXG];
__device__ int    g_flags;

// -------- index helpers --------
__device__ __forceinline__ int idx_at(const void* p, long long i, int is64) {
    return is64 ? (int)((const long long*)p)[i] : ((const int*)p)[i];
}

// -------- detect (thread 0) + init, fused --------
__global__ void k_detect_init(const void* ei, int twoE, const void* batch,
                              float* out, int out_elems, int n) {
    int i = blockIdx.x * blockDim.x + threadIdx.x;
    if (i < n)         g_deg[i] = 0;
    if (i < MAXG)      g_cnt[i] = 0;
    if (i < out_elems) out[i]   = 0.0f;
    if (blockIdx.x == 0 && threadIdx.x == 0) {
        const int* e32 = (const int*)ei;
        const int* b32 = (const int*)batch;
        int e64 = 1, b64 = 1;
        int m1 = (twoE / 2) & ~1;
        for (int k = 1; k < 64; k += 2)      if (e32[k] != 0)      { e64 = 0; break; }
        if (e64) for (int k = 1; k < 64; k += 2) if (e32[m1 + k] != 0) { e64 = 0; break; }
        int m2 = (n / 2) & ~1;
        for (int k = 1; k < 64 && m2 + k < n; k += 2) if (b32[m2 + k] != 0) { b64 = 0; break; }
        g_flags = (e64 ? 1 : 0) | (b64 ? 2 : 0);
    }
}

// -------- degree histogram (records per-edge rank) + per-graph counts --------
__global__ void k_degcnt(const void* ei, int E, const void* batch, int n) {
    int i = blockIdx.x * blockDim.x + threadIdx.x;
    int fl = g_flags;
    if (i < E) {
        int d = idx_at(ei, (long long)E + i, fl & 1);
        g_eslot[i] = atomicAdd(&g_deg[d], 1);
    }
    if (i < n) {
        int b = idx_at(batch, i, (fl >> 1) & 1);
        atomicAdd(&g_cnt[b], 1);
    }
}

// -------- scan stage 1: partial exclusive prefix + dis = rsqrt(deg+1) --------
__global__ void k_scan1(int n) {
    __shared__ int s[256];
    int blk = blockIdx.x;
    int base = blk * 1024;
    int t = threadIdx.x;
    int v[4]; int sum = 0;
#pragma unroll
    for (int j = 0; j < 4; j++) {
        int i = base + t * 4 + j;
        v[j] = (i < n) ? g_deg[i] : 0;
        sum += v[j];
    }
    s[t] = sum;
    __syncthreads();
    for (int off = 1; off < 256; off <<= 1) {
        int y = (t >= off) ? s[t - off] : 0;
        __syncthreads();
        s[t] += y;
        __syncthreads();
    }
    int run = s[t] - sum;
#pragma unroll
    for (int j = 0; j < 4; j++) {
        int i = base + t * 4 + j;
        if (i < n) {
            g_rowoff[i] = run;
            g_dis[i] = rsqrtf((float)(v[j] + 1));
        }
        run += v[j];
    }
    if (t == 255) g_blk[blk] = s[255];
}

// -------- scan stage 2: exclusive scan of block totals --------
__global__ void k_scan2(int nblk) {
    __shared__ int s[NBLK_SCAN];
    int t = threadIdx.x;
    int v = (t < nblk) ? g_blk[t] : 0;
    s[t] = v;
    __syncthreads();
    for (int off = 1; off < NBLK_SCAN; off <<= 1) {
        int y = (t >= off) ? s[t - off] : 0;
        __syncthreads();
        s[t] += y;
        __syncthreads();
    }
    g_blkoff[t] = s[t] - v;
}

// -------- place: computed store, no atomics --------
__global__ void k_place(const void* __restrict__ ei, int E) {
    int e = blockIdx.x * blockDim.x + threadIdx.x;
    if (e >= E) return;
    int fl = g_flags & 1;
    int s = idx_at(ei, e, fl);
    int d = idx_at(ei, (long long)E + e, fl);
    int pos = g_rowoff[d] + g_blkoff[d >> 10] + g_eslot[e];
    g_ssrc[pos] = s;
}

// -------- fp16 mma m16n8k16 --------
__device__ __forceinline__ void mma_f16(float* c, const unsigned* a, const unsigned* b) {
    asm volatile("mma.sync.aligned.m16n8k16.row.col.f32.f16.f16.f32 "
                 "{%0,%1,%2,%3}, {%4,%5,%6,%7}, {%8,%9}, {%0,%1,%2,%3};"
                 : "+f"(c[0]), "+f"(c[1]), "+f"(c[2]), "+f"(c[3])
                 : "r"(a[0]), "r"(a[1]), "r"(a[2]), "r"(a[3]),
                   "r"(b[0]), "r"(b[1]));
}

__device__ __forceinline__ unsigned h2u(__half2 h) { return *(unsigned*)&h; }

__device__ __forceinline__ float4 h4tof4(uint2 r) {
    float2 fa = __half22float2(*(__half2*)&r.x);
    float2 fb = __half22float2(*(__half2*)&r.y);
    return make_float4(fa.x, fa.y, fb.x, fb.y);
}

// -------- GEMM (fp16 m16n8k16): Th = half((A @ W) * dis) --------
// LAYER==1: A = external x.  LAYER==2: A = relu(dis*g_A1 + b_in) on the fly.
template <int LAYER>
__global__ void __launch_bounds__(256) k_gemm_tc(const float* __restrict__ Aext,
                                                 const float* __restrict__ W,
                                                 const float* __restrict__ bin,
                                                 int n) {
    __shared__ __half As[128][40];   // [row][k]; frag bank = 20*lq+lr distinct
    __shared__ __half Ws[32][136];

    const float* __restrict__ A = (LAYER == 1) ? Aext : g_A1;

    const int tid = threadIdx.x;
    const int lane = tid & 31;
    const int wid = tid >> 5;
    const int warp_m = wid & 1;
    const int warp_n = wid >> 1;
    const int row0 = blockIdx.x * 128;
    const int lq = lane >> 2;
    const int lr = lane & 3;

    float c[4][4][4];
#pragma unroll
    for (int i = 0; i < 4; i++)
#pragma unroll
        for (int j = 0; j < 4; j++)
#pragma unroll
            for (int r = 0; r < 4; r++) c[i][j][r] = 0.0f;

    for (int k0 = 0; k0 < F; k0 += 32) {
#pragma unroll
        for (int it = 0; it < 4; it++) {
            int idx = tid + it * 256;
            int k = idx >> 5, c4 = idx & 31;
            float4 w = ((const float4*)(W + (size_t)(k0 + k) * F))[c4];
            *(__half2*)&Ws[k][c4 * 4 + 0] = __floats2half2_rn(w.x, w.y);
            *(__half2*)&Ws[k][c4 * 4 + 2] = __floats2half2_rn(w.z, w.w);
        }
#pragma unroll
        for (int it = 0; it < 4; it++) {
            int idx = tid + it * 256;
            int r = idx >> 3, kp = idx & 7;
            int row = row0 + r;
            float4 a = make_float4(0.f, 0.f, 0.f, 0.f);
            if (row < n) a = ((const float4*)(A + (size_t)row * F + k0))[kp];
            if (LAYER == 2) {
                float dv = (row < n) ? g_dis[row] : 0.f;
                int kk = k0 + kp * 4;
                a.x = fmaxf(fmaf(dv, a.x, bin[kk + 0]), 0.f);
                a.y = fmaxf(fmaf(dv, a.y, bin[kk + 1]), 0.f);
                a.z = fmaxf(fmaf(dv, a.z, bin[kk + 2]), 0.f);
                a.w = fmaxf(fmaf(dv, a.w, bin[kk + 3]), 0.f);
            }
            *(__half2*)&As[r][kp * 4 + 0] = __floats2half2_rn(a.x, a.y);
            *(__half2*)&As[r][kp * 4 + 2] = __floats2half2_rn(a.z, a.w);
        }
        __syncthreads();

#pragma unroll
        for (int ks = 0; ks < 2; ks++) {
            const int kk = ks * 16;
            unsigned ar[4][4];
#pragma unroll
            for (int tm = 0; tm < 4; tm++) {
                int r = warp_m * 64 + tm * 16 + lq;
                ar[tm][0] = *(unsigned*)&As[r][kk + 2 * lr];
                ar[tm][1] = *(unsigned*)&As[r + 8][kk + 2 * lr];
                ar[tm][2] = *(unsigned*)&As[r][kk + 2 * lr + 8];
                ar[tm][3] = *(unsigned*)&As[r + 8][kk + 2 * lr + 8];
            }
            unsigned br[4][2];
#pragma unroll
            for (int tn = 0; tn < 4; tn++) {
                int col = warp_n * 32 + tn * 8 + lq;
                br[tn][0] = h2u(__halves2half2(Ws[kk + 2 * lr][col],
                                               Ws[kk + 2 * lr + 1][col]));
                br[tn][1] = h2u(__halves2half2(Ws[kk + 2 * lr + 8][col],
                                               Ws[kk + 2 * lr + 9][col]));
            }
#pragma unroll
            for (int tn = 0; tn < 4; tn++)
#pragma unroll
                for (int tm = 0; tm < 4; tm++)
                    mma_f16(c[tm][tn], ar[tm], br[tn]);
        }
        __syncthreads();
    }

#pragma unroll
    for (int tm = 0; tm < 4; tm++) {
        int r0 = row0 + warp_m * 64 + tm * 16 + lq;
        int r1 = r0 + 8;
        float d0 = (r0 < n) ? g_dis[r0] : 0.f;
        float d1 = (r1 < n) ? g_dis[r1] : 0.f;
#pragma unroll
        for (int tn = 0; tn < 4; tn++) {
            int col = warp_n * 32 + tn * 8 + lr * 2;
            if (r0 < n)
                *(__half2*)(g_Th + (size_t)r0 * F + col) =
                    __floats2half2_rn(c[tm][tn][0] * d0, c[tm][tn][1] * d0);
            if (r1 < n)
                *(__half2*)(g_Th + (size_t)r1 * F + col) =
                    __floats2half2_rn(c[tm][tn][2] * d1, c[tm][tn][3] * d1);
        }
    }
}

// -------- CSR aggregation (fp16 gather, fp32 accumulate); warp per node --------
// LAYER==1: write g_A1 (fp32).  LAYER==2: fused pooling -> red.add into out.
template <int LAYER>
__global__ void __launch_bounds__(256) k_agg(int n, const void* __restrict__ batch,
                                             const float* __restrict__ b2,
                                             float* __restrict__ out) {
    const __half* __restrict__ T = g_Th;
    int w = (blockIdx.x * blockDim.x + threadIdx.x) >> 5;
    int lane = threadIdx.x & 31;
    if (w >= n) return;

    int beg = g_rowoff[w] + g_blkoff[w >> 10];
    int end;
    if (w + 1 < n) end = g_rowoff[w + 1] + g_blkoff[(w + 1) >> 10];
    else           end = beg + g_deg[w];

    float4 acc = h4tof4(((const uint2*)(T + (size_t)w * F))[lane]);   // self loop

    int j = beg;
    for (; j + 8 <= end; j += 8) {
        int s0 = g_ssrc[j],     s1 = g_ssrc[j + 1], s2 = g_ssrc[j + 2], s3 = g_ssrc[j + 3];
        int s4 = g_ssrc[j + 4], s5 = g_ssrc[j + 5], s6 = g_ssrc[j + 6], s7 = g_ssrc[j + 7];
        float4 a = h4tof4(((const uint2*)(T + (size_t)s0 * F))[lane]);
        float4 b = h4tof4(((const uint2*)(T + (size_t)s1 * F))[lane]);
        float4 c = h4tof4(((const uint2*)(T + (size_t)s2 * F))[lane]);
        float4 d = h4tof4(((const uint2*)(T + (size_t)s3 * F))[lane]);
        float4 e = h4tof4(((const uint2*)(T + (size_t)s4 * F))[lane]);
        float4 f = h4tof4(((const uint2*)(T + (size_t)s5 * F))[lane]);
        float4 g = h4tof4(((const uint2*)(T + (size_t)s6 * F))[lane]);
        float4 h = h4tof4(((const uint2*)(T + (size_t)s7 * F))[lane]);
        acc.x += (a.x + b.x) + (c.x + d.x) + ((e.x + f.x) + (g.x + h.x));
        acc.y += (a.y + b.y) + (c.y + d.y) + ((e.y + f.y) + (g.y + h.y));
        acc.z += (a.z + b.z) + (c.z + d.z) + ((e.z + f.z) + (g.z + h.z));
        acc.w += (a.w + b.w) + (c.w + d.w) + ((e.w + f.w) + (g.w + h.w));
    }
    for (; j + 4 <= end; j += 4) {
        int s0 = g_ssrc[j], s1 = g_ssrc[j + 1], s2 = g_ssrc[j + 2], s3 = g_ssrc[j + 3];
        float4 a = h4tof4(((const uint2*)(T + (size_t)s0 * F))[lane]);
        float4 b = h4tof4(((const uint2*)(T + (size_t)s1 * F))[lane]);
        float4 c = h4tof4(((const uint2*)(T + (size_t)s2 * F))[lane]);
        float4 d = h4tof4(((const uint2*)(T + (size_t)s3 * F))[lane]);
        acc.x += (a.x + b.x) + (c.x + d.x);
        acc.y += (a.y + b.y) + (c.y + d.y);
        acc.z += (a.z + b.z) + (c.z + d.z);
        acc.w += (a.w + b.w) + (c.w + d.w);
    }
    for (; j < end; j++) {
        int s = g_ssrc[j];
        float4 a = h4tof4(((const uint2*)(T + (size_t)s * F))[lane]);
        acc.x += a.x; acc.y += a.y; acc.z += a.z; acc.w += a.w;
    }

    if (LAYER == 1) {
        ((float4*)(g_A1 + (size_t)w * F))[lane] = acc;
    } else {
        int g = idx_at(batch, w, (g_flags >> 1) & 1);
        float dv = g_dis[w];
        float4 bb = ((const float4*)b2)[lane];
        float4 r;
        r.x = fmaxf(fmaf(dv, acc.x, bb.x), 0.f);
        r.y = fmaxf(fmaf(dv, acc.y, bb.y), 0.f);
        r.z = fmaxf(fmaf(dv, acc.z, bb.z), 0.f);
        r.w = fmaxf(fmaf(dv, acc.w, bb.w), 0.f);
        float* p = out + (size_t)g * F + lane * 4;
        asm volatile("red.global.add.v4.f32 [%0], {%1,%2,%3,%4};"
                     :: "l"(p), "f"(r.x), "f"(r.y), "f"(r.z), "f"(r.w)
                     : "memory");
    }
}

__global__ void k_div(float* out, int total) {
    int i = blockIdx.x * blockDim.x + threadIdx.x;
    if (i < total) {
        int g = i >> 7;
        int c = g_cnt[g];
        out[i] = out[i] / (float)(c > 1 ? c : 1);
    }
}

// -------- launch --------
extern "C" void kernel_launch(void* const* d_in, const int* in_sizes, int n_in,
                              void* d_out, int out_size) {
    const float* x   = (const float*)d_in[0];
    const void*  ei  = d_in[1];
    const void*  bat = d_in[2];
    const float* W1  = (const float*)d_in[3];
    const float* b1  = (const float*)d_in[4];
    const float* W2  = (const float*)d_in[5];
    const float* b2  = (const float*)d_in[6];
    float* out = (float*)d_out;

    int n = in_sizes[2];
    if (n > MAXN) n = MAXN;
    int E = in_sizes[1] / 2;
    if (E > MAXE) E = MAXE;

    int initN = (n > out_size) ? n : out_size;
    k_detect_init<<<(initN + 255) / 256, 256>>>(ei, 2 * E, bat, out, out_size, n);

    int degN = (E > n) ? E : n;
    k_degcnt<<<(degN + 255) / 256, 256>>>(ei, E, bat, n);

    int nblk = (n + 1023) / 1024;
    k_scan1<<<nblk, 256>>>(n);
    k_scan2<<<1, NBLK_SCAN>>>(nblk);

    k_place<<<(E + 255) / 256, 256>>>(ei, E);

    int gblocks = (n + 127) / 128;
    int ablocks = (n + 7) / 8;

    k_gemm_tc<1><<<gblocks, 256>>>(x, W1, b1, n);
    k_agg<1><<<ablocks, 256>>>(n, bat, b2, out);
    k_gemm_tc<2><<<gblocks, 256>>>(nullptr, W2, b1, n);
    k_agg<2><<<ablocks, 256>>>(n, bat, b2, out);
    k_div<<<(out_size + 255) / 256, 256>>>(out, out_size);
}